// round 2
// baseline (speedup 1.0000x reference)
#include <cuda_runtime.h>
#include <stdint.h>

#define N_BCH 8
#define N_ATM 10000
#define N_ELM 100
#define THREADS 256
#define GRID_MAIN 1184

// u8 element-type table (80 KB) — kept L1-resident by streaming edges with .cs
__device__ uint8_t g_elm8[N_BCH * N_ATM];

// ---------------------------------------------------------------------------
// Prepass: zero outputs, convert elm int32 -> uint8.
// ---------------------------------------------------------------------------
__global__ void prep_kernel(const int* __restrict__ elm, float* __restrict__ out)
{
    int tid = blockIdx.x * blockDim.x + threadIdx.x;
    if (tid < N_BCH) out[tid] = 0.0f;
    for (int i = tid; i < N_BCH * N_ATM; i += gridDim.x * blockDim.x)
        g_elm8[i] = (uint8_t)elm[i];
}

// ---------------------------------------------------------------------------
// Main kernel
// ---------------------------------------------------------------------------
__device__ __forceinline__ void edge_op(int n, int i, int j, float s,
                                        const float* __restrict__ k_s,
                                        const float* __restrict__ r_s,
                                        float* __restrict__ acc_base)
{
    int a = __ldg(&g_elm8[n * N_ATM + i]);
    int b = __ldg(&g_elm8[n * N_ATM + j]);
    float R   = r_s[a] + r_s[b];
    float dis = sqrtf(s);
    if (dis < R) {
        float kk = k_s[a] + k_s[b];
        float d  = dis - R;
        acc_base[n << 5] += kk * d * d;
    }
}

__global__ void __launch_bounds__(THREADS)
close_penalty_kernel(const int4*  __restrict__ edge_n4,
                     const int4*  __restrict__ edge_i4,
                     const int4*  __restrict__ edge_j4,
                     const float4* __restrict__ sod4,
                     const int*   __restrict__ edge_n,
                     const int*   __restrict__ edge_i,
                     const int*   __restrict__ edge_j,
                     const float* __restrict__ sod,
                     const float* __restrict__ k,
                     const float* __restrict__ radius,
                     float* __restrict__ out,
                     int nvec, int E)
{
    __shared__ float k_s[N_ELM];
    __shared__ float r_s[N_ELM];
    __shared__ float acc[8 * THREADS];   // [warp][bin][lane], conflict-free

    int tid  = threadIdx.x;
    int lane = tid & 31;
    int wid  = tid >> 5;

    if (tid < N_ELM) { k_s[tid] = k[tid]; r_s[tid] = radius[tid]; }
    #pragma unroll
    for (int b = 0; b < 8; b++) acc[b * THREADS + tid] = 0.0f;
    __syncthreads();

    float* acc_base = &acc[(wid << 8) | lane];   // + (n<<5) per edge

    int gtid   = blockIdx.x * blockDim.x + tid;
    int stride = gridDim.x * blockDim.x;

    int v = gtid;
    // 2x unrolled: 8 independent 16B streaming loads in flight per warp.
    for (; v + stride < nvec; v += 2 * stride) {
        int v2 = v + stride;
        int4   en0 = __ldcs(&edge_n4[v]);
        int4   ei0 = __ldcs(&edge_i4[v]);
        int4   ej0 = __ldcs(&edge_j4[v]);
        float4 s0  = __ldcs(&sod4[v]);
        int4   en1 = __ldcs(&edge_n4[v2]);
        int4   ei1 = __ldcs(&edge_i4[v2]);
        int4   ej1 = __ldcs(&edge_j4[v2]);
        float4 s1  = __ldcs(&sod4[v2]);

        edge_op(en0.x, ei0.x, ej0.x, s0.x, k_s, r_s, acc_base);
        edge_op(en0.y, ei0.y, ej0.y, s0.y, k_s, r_s, acc_base);
        edge_op(en0.z, ei0.z, ej0.z, s0.z, k_s, r_s, acc_base);
        edge_op(en0.w, ei0.w, ej0.w, s0.w, k_s, r_s, acc_base);
        edge_op(en1.x, ei1.x, ej1.x, s1.x, k_s, r_s, acc_base);
        edge_op(en1.y, ei1.y, ej1.y, s1.y, k_s, r_s, acc_base);
        edge_op(en1.z, ei1.z, ej1.z, s1.z, k_s, r_s, acc_base);
        edge_op(en1.w, ei1.w, ej1.w, s1.w, k_s, r_s, acc_base);
    }
    for (; v < nvec; v += stride) {
        int4   en = __ldcs(&edge_n4[v]);
        int4   ei = __ldcs(&edge_i4[v]);
        int4   ej = __ldcs(&edge_j4[v]);
        float4 s  = __ldcs(&sod4[v]);
        edge_op(en.x, ei.x, ej.x, s.x, k_s, r_s, acc_base);
        edge_op(en.y, ei.y, ej.y, s.y, k_s, r_s, acc_base);
        edge_op(en.z, ei.z, ej.z, s.z, k_s, r_s, acc_base);
        edge_op(en.w, ei.w, ej.w, s.w, k_s, r_s, acc_base);
    }

    // Scalar tail
    int t = nvec * 4 + gtid;
    if (t < E)
        edge_op(edge_n[t], edge_i[t], edge_j[t], sod[t], k_s, r_s, acc_base);

    __syncthreads();

    // Reduce: thread t handles (bin = t>>5, lane = t&31); sum over 8 warps,
    // then warp-shuffle reduce; conflict-free smem reads.
    int bin = tid >> 5;
    float sum = 0.0f;
    #pragma unroll
    for (int w = 0; w < 8; w++)
        sum += acc[(w << 8) + (bin << 5) + lane];
    #pragma unroll
    for (int off = 16; off > 0; off >>= 1)
        sum += __shfl_down_sync(0xFFFFFFFFu, sum, off);
    if (lane == 0)
        atomicAdd(&out[bin], sum);
}

// ---------------------------------------------------------------------------
// Launch
// ---------------------------------------------------------------------------
extern "C" void kernel_launch(void* const* d_in, const int* in_sizes, int n_in,
                              void* d_out, int out_size)
{
    const int*   elm    = (const int*)  d_in[0];
    const int*   edge_n = (const int*)  d_in[1];
    const int*   edge_i = (const int*)  d_in[2];
    const int*   edge_j = (const int*)  d_in[3];
    const float* sod    = (const float*)d_in[4];
    const float* k      = (const float*)d_in[5];
    const float* radius = (const float*)d_in[6];
    float* out = (float*)d_out;

    int E    = in_sizes[1];
    int nvec = E >> 2;

    prep_kernel<<<(N_BCH * N_ATM + 255) / 256, 256>>>(elm, out);

    int grid = GRID_MAIN;
    int need = (nvec + THREADS - 1) / THREADS;
    if (need < grid) grid = need > 0 ? need : 1;

    close_penalty_kernel<<<grid, THREADS>>>(
        (const int4*)edge_n, (const int4*)edge_i, (const int4*)edge_j,
        (const float4*)sod,
        edge_n, edge_i, edge_j, sod,
        k, radius,
        out, nvec, E);
}

// round 3
// speedup vs baseline: 1.4049x; 1.4049x over previous
#include <cuda_runtime.h>
#include <stdint.h>

#define N_BCH 8
#define N_ATM 10000
#define N_ELM 100
#define THREADS 256
#define GRID_MAIN 296            // 2 persistent CTAs per SM (148 SMs)

#define ELM_BYTES (N_BCH * N_ATM)              // 80000
#define SMEM_LUT   0                            // float2[128] -> 1024 B
#define SMEM_ACC   1024                         // 8*256 floats -> 8192 B
#define SMEM_ELM   (1024 + 8 * THREADS * 4)     // 80000 B
#define SMEM_TOTAL (SMEM_ELM + ELM_BYTES)       // 89216 B

// Global staging for the u8 element table (built once per launch by prepass).
__device__ uint8_t g_elm8[ELM_BYTES];

// ---------------------------------------------------------------------------
// Prepass: zero outputs, convert elm int32 -> uint8 (values < 100).
// ---------------------------------------------------------------------------
__global__ void prep_kernel(const int* __restrict__ elm, float* __restrict__ out)
{
    int tid = blockIdx.x * blockDim.x + threadIdx.x;
    if (tid < N_BCH) out[tid] = 0.0f;
    for (int i = tid; i < ELM_BYTES; i += gridDim.x * blockDim.x)
        g_elm8[i] = (uint8_t)elm[i];
}

// ---------------------------------------------------------------------------
// Main kernel: all gathers served from shared memory.
// ---------------------------------------------------------------------------
__device__ __forceinline__ void edge_op(int n, int i, int j, float s,
                                        const uint8_t* __restrict__ elm_s,
                                        const float2* __restrict__ lut,
                                        float* __restrict__ acc_base)
{
    int a = elm_s[n * N_ATM + i];
    int b = elm_s[n * N_ATM + j];
    float2 pa = lut[a];
    float2 pb = lut[b];
    float R   = pa.y + pb.y;
    float dis = sqrtf(s);
    if (dis < R) {
        float d = dis - R;
        acc_base[n << 5] += (pa.x + pb.x) * d * d;
    }
}

__global__ void __launch_bounds__(THREADS)
close_penalty_kernel(const int4*  __restrict__ edge_n4,
                     const int4*  __restrict__ edge_i4,
                     const int4*  __restrict__ edge_j4,
                     const float4* __restrict__ sod4,
                     const int*   __restrict__ edge_n,
                     const int*   __restrict__ edge_i,
                     const int*   __restrict__ edge_j,
                     const float* __restrict__ sod,
                     const float* __restrict__ k,
                     const float* __restrict__ radius,
                     float* __restrict__ out,
                     int nvec, int E)
{
    extern __shared__ char smem[];
    float2*  lut   = (float2*)(smem + SMEM_LUT);
    float*   acc   = (float*) (smem + SMEM_ACC);
    uint8_t* elm_s = (uint8_t*)(smem + SMEM_ELM);

    int tid  = threadIdx.x;
    int lane = tid & 31;
    int wid  = tid >> 5;

    if (tid < N_ELM) lut[tid] = make_float2(k[tid], radius[tid]);
    #pragma unroll
    for (int b = 0; b < 8; b++) acc[b * THREADS + tid] = 0.0f;

    // Copy 80 KB u8 element table into shared memory (16B chunks).
    {
        const int4* src = (const int4*)g_elm8;
        int4*       dst = (int4*)elm_s;
        #pragma unroll
        for (int i = tid; i < ELM_BYTES / 16; i += THREADS)
            dst[i] = __ldg(&src[i]);
    }
    __syncthreads();

    float* acc_base = &acc[(wid << 8) | lane];   // + (n<<5) per edge

    int gtid   = blockIdx.x * blockDim.x + tid;
    int stride = gridDim.x * blockDim.x;

    int v = gtid;
    // 2x unrolled: 8 independent 16B streaming loads in flight per warp.
    for (; v + stride < nvec; v += 2 * stride) {
        int v2 = v + stride;
        int4   en0 = __ldcs(&edge_n4[v]);
        int4   ei0 = __ldcs(&edge_i4[v]);
        int4   ej0 = __ldcs(&edge_j4[v]);
        float4 s0  = __ldcs(&sod4[v]);
        int4   en1 = __ldcs(&edge_n4[v2]);
        int4   ei1 = __ldcs(&edge_i4[v2]);
        int4   ej1 = __ldcs(&edge_j4[v2]);
        float4 s1  = __ldcs(&sod4[v2]);

        edge_op(en0.x, ei0.x, ej0.x, s0.x, elm_s, lut, acc_base);
        edge_op(en0.y, ei0.y, ej0.y, s0.y, elm_s, lut, acc_base);
        edge_op(en0.z, ei0.z, ej0.z, s0.z, elm_s, lut, acc_base);
        edge_op(en0.w, ei0.w, ej0.w, s0.w, elm_s, lut, acc_base);
        edge_op(en1.x, ei1.x, ej1.x, s1.x, elm_s, lut, acc_base);
        edge_op(en1.y, ei1.y, ej1.y, s1.y, elm_s, lut, acc_base);
        edge_op(en1.z, ei1.z, ej1.z, s1.z, elm_s, lut, acc_base);
        edge_op(en1.w, ei1.w, ej1.w, s1.w, elm_s, lut, acc_base);
    }
    for (; v < nvec; v += stride) {
        int4   en = __ldcs(&edge_n4[v]);
        int4   ei = __ldcs(&edge_i4[v]);
        int4   ej = __ldcs(&edge_j4[v]);
        float4 s  = __ldcs(&sod4[v]);
        edge_op(en.x, ei.x, ej.x, s.x, elm_s, lut, acc_base);
        edge_op(en.y, ei.y, ej.y, s.y, elm_s, lut, acc_base);
        edge_op(en.z, ei.z, ej.z, s.z, elm_s, lut, acc_base);
        edge_op(en.w, ei.w, ej.w, s.w, elm_s, lut, acc_base);
    }

    // Scalar tail
    int t = nvec * 4 + gtid;
    if (t < E)
        edge_op(edge_n[t], edge_i[t], edge_j[t], sod[t], elm_s, lut, acc_base);

    __syncthreads();

    // Reduce: thread t owns (bin = t>>5, lane); sum over 8 warps, shuffle-reduce.
    int bin = tid >> 5;
    float sum = 0.0f;
    #pragma unroll
    for (int w = 0; w < 8; w++)
        sum += acc[(w << 8) + (bin << 5) + lane];
    #pragma unroll
    for (int off = 16; off > 0; off >>= 1)
        sum += __shfl_down_sync(0xFFFFFFFFu, sum, off);
    if (lane == 0)
        atomicAdd(&out[bin], sum);
}

// ---------------------------------------------------------------------------
// Launch
// ---------------------------------------------------------------------------
extern "C" void kernel_launch(void* const* d_in, const int* in_sizes, int n_in,
                              void* d_out, int out_size)
{
    const int*   elm    = (const int*)  d_in[0];
    const int*   edge_n = (const int*)  d_in[1];
    const int*   edge_i = (const int*)  d_in[2];
    const int*   edge_j = (const int*)  d_in[3];
    const float* sod    = (const float*)d_in[4];
    const float* k      = (const float*)d_in[5];
    const float* radius = (const float*)d_in[6];
    float* out = (float*)d_out;

    int E    = in_sizes[1];
    int nvec = E >> 2;

    cudaFuncSetAttribute(close_penalty_kernel,
                         cudaFuncAttributeMaxDynamicSharedMemorySize, SMEM_TOTAL);

    prep_kernel<<<(ELM_BYTES + 255) / 256, 256>>>(elm, out);

    int grid = GRID_MAIN;
    int need = (nvec + THREADS - 1) / THREADS;
    if (need < grid) grid = need > 0 ? need : 1;

    close_penalty_kernel<<<grid, THREADS, SMEM_TOTAL>>>(
        (const int4*)edge_n, (const int4*)edge_i, (const int4*)edge_j,
        (const float4*)sod,
        edge_n, edge_i, edge_j, sod,
        k, radius,
        out, nvec, E);
}